// round 3
// baseline (speedup 1.0000x reference)
#include <cuda_runtime.h>
#include <cstdint>

#define THREADS 256
#define BT 64

// sB slice loader: U[c][a] rows kb*16..kb*16+15, first 256 of 272 cols -> [16][256] floats
__device__ __forceinline__ void storeB(float4* dst4, const float* __restrict__ Uca,
                                       int kb, int tid) {
    #pragma unroll
    for (int i = 0; i < 4; i++) {
        int idx = tid + i * THREADS;          // float4 index 0..1023
        int kk = idx >> 6, r4 = idx & 63;
        dst4[idx] = ((const float4*)(Uca + (size_t)(kb * 16 + kk) * 272))[r4];
    }
}

// Grid: 256 CTAs x 64 batch rows. Block 256 threads: ty=tid/16 (4 m-rows each), tx=tid%16.
// Thread (ty,tx) computes ris columns r = i*16+tx for i=0..15 (scan-matrix column tx).
__global__ __launch_bounds__(THREADS, 2)
void tt_fused_kernel(const float* __restrict__ nh,   // [16384][8][256]
                     const float* __restrict__ te,   // [16384][64]
                     const float* __restrict__ U,    // [8][4][256][272]
                     const float* __restrict__ bB,   // [8][4][1][272]
                     const float* __restrict__ Ut,   // [4][64][16]
                     const float* __restrict__ bt,   // [4][1][16]
                     const float* __restrict__ Uo,   // [4][16][256]
                     const float* __restrict__ bo,   // [4][1][256]
                     float* __restrict__ out)        // [16384][1024]
{
    extern __shared__ float smem[];
    float* sA  = smem;                         // [64][256]  16384 f
    float* sB0 = smem + 16384;                 // [16][256]   4096 f
    float* sB1 = smem + 16384 + 4096;          // [16][256]   4096 f
    float* sX  = smem + 16384 + 8192;          // [64][64] te tile, later [64][4][16] carries

    const int tid = threadIdx.x;
    const int tx  = tid & 15;
    const int ty  = tid >> 4;
    const int b0  = blockIdx.x * BT;

    float4* sA4 = (float4*)sA;
    float4* sX4 = (float4*)sX;
    float*  sBb[2] = { sB0, sB1 };
    float4* sBb4[2] = { (float4*)sB0, (float4*)sB1 };

    // ---- load type-embedding tile [64][64] into sX ----
    #pragma unroll
    for (int i = 0; i < 4; i++) {
        int idx = tid + i * THREADS;           // float4 index 0..1023
        int m = idx >> 4, t4 = idx & 15;
        sX4[idx] = ((const float4*)(te + (size_t)(b0 + m) * 64))[t4];
    }
    __syncthreads();

    // ---- v0 = te @ U_type + b_type : carry component tx per (a, mi), in registers ----
    float vcar[4][4];
    #pragma unroll
    for (int a = 0; a < 4; a++) {
        float btv = __ldg(bt + a * 16 + tx);
        float s0 = btv, s1 = btv, s2 = btv, s3 = btv;
        const float* ut = Ut + a * 64 * 16 + tx;
        const float* x0 = sX + (ty * 4 + 0) * 64;
        const float* x1 = sX + (ty * 4 + 1) * 64;
        const float* x2 = sX + (ty * 4 + 2) * 64;
        const float* x3 = sX + (ty * 4 + 3) * 64;
        #pragma unroll 8
        for (int t = 0; t < 64; t++) {
            float u = __ldg(ut + t * 16);
            s0 += x0[t] * u; s1 += x1[t] * u; s2 += x2[t] * u; s3 += x3[t] * u;
        }
        vcar[a][0] = s0; vcar[a][1] = s1; vcar[a][2] = s2; vcar[a][3] = s3;
    }
    // sX stays as te until overwritten by carries at the end; no further reads of te.

    // ---- main loop: c outer (sequential scan), a middle, kb inner with double-buffered sB ----
    for (int c = 0; c < 8; c++) {
        __syncthreads();  // prev c readers of sA (and sB) done
        // load nh[:, c, :] -> sA
        #pragma unroll
        for (int i = 0; i < 16; i++) {
            int idx = tid + i * THREADS;       // float4 index 0..4095
            int m = idx >> 6, k4 = idx & 63;
            sA4[idx] = ((const float4*)(nh + ((size_t)(b0 + m) * 8 + c) * 256))[k4];
        }
        if (c == 0) storeB(sBb4[0], U, 0, tid);   // prime slice s=0

        #pragma unroll 1
        for (int a = 0; a < 4; a++) {
            float acc[4][16];
            #pragma unroll
            for (int mi = 0; mi < 4; mi++)
                #pragma unroll
                for (int i = 0; i < 16; i++) acc[mi][i] = 0.f;

            #pragma unroll 1
            for (int kb = 0; kb < 16; kb++) {
                const int s = ((c * 4 + a) << 4) | kb;   // linear slice id 0..511
                const int cur = kb & 1;
                __syncthreads();  // slice s visible in buf[cur]; buf[1-cur] free

                if (s + 1 < 512) {
                    const float* UcaN = U + (size_t)((s + 1) >> 4) * (256 * 272);
                    storeB(sBb4[(kb + 1) & 1], UcaN, (s + 1) & 15, tid);
                }

                const float* Bb = sBb[cur];
                #pragma unroll
                for (int kkg = 0; kkg < 4; kkg++) {
                    float4 av0 = sA4[(ty * 4 + 0) * 64 + kb * 4 + kkg];
                    float4 av1 = sA4[(ty * 4 + 1) * 64 + kb * 4 + kkg];
                    float4 av2 = sA4[(ty * 4 + 2) * 64 + kb * 4 + kkg];
                    float4 av3 = sA4[(ty * 4 + 3) * 64 + kb * 4 + kkg];
                    #pragma unroll
                    for (int kq = 0; kq < 4; kq++) {
                        const int kk = kkg * 4 + kq;
                        const float a0 = (kq == 0) ? av0.x : (kq == 1) ? av0.y : (kq == 2) ? av0.z : av0.w;
                        const float a1 = (kq == 0) ? av1.x : (kq == 1) ? av1.y : (kq == 2) ? av1.z : av1.w;
                        const float a2 = (kq == 0) ? av2.x : (kq == 1) ? av2.y : (kq == 2) ? av2.z : av2.w;
                        const float a3 = (kq == 0) ? av3.x : (kq == 1) ? av3.y : (kq == 2) ? av3.z : av3.w;
                        const float* br = Bb + kk * 256 + tx;
                        #pragma unroll
                        for (int i = 0; i < 16; i++) {
                            float u = br[i * 16];      // lanes consecutive: conflict-free
                            acc[0][i] += a0 * u;
                            acc[1][i] += a1 * u;
                            acc[2][i] += a2 * u;
                            acc[3][i] += a3 * u;
                        }
                    }
                }
            }

            // + bias b[c][a][0][r], r = i*16+tx
            const float* bp = bB + (size_t)(c * 4 + a) * 272 + tx;
            #pragma unroll
            for (int i = 0; i < 16; i++) {
                float bb = __ldg(bp + i * 16);
                #pragma unroll
                for (int mi = 0; mi < 4; mi++) acc[mi][i] += bb;
            }

            // scan: v_new[tx] = sum_i (v[i] + [i==15]) * M[i][tx]; M[i][tx] = acc[mi][i]
            #pragma unroll
            for (int mi = 0; mi < 4; mi++) {
                float nv = 0.f;
                #pragma unroll
                for (int i = 0; i < 16; i++) {
                    float coef = __shfl_sync(0xffffffffu, vcar[a][mi], i, 16);
                    if (i == 15) coef += 1.0f;
                    nv += coef * acc[mi][i];
                }
                vcar[a][mi] = nv;
            }
        }
    }

    // ---- dump carries to sX as [m][a][16] ----
    __syncthreads();  // done with te contents / prior sB readers
    #pragma unroll
    for (int a = 0; a < 4; a++)
        #pragma unroll
        for (int mi = 0; mi < 4; mi++)
            sX[((ty * 4 + mi) * 4 + a) * 16 + tx] = vcar[a][mi];
    __syncthreads();

    // ---- output projection: out[m][a*256+hh] = v[m][a] . Uo[a][:,hh] + bo[a][hh] ----
    #pragma unroll 1
    for (int i = 0; i < 4; i++) {
        int q  = tid + i * THREADS;            // 0..1023
        int a  = q >> 8, hh = q & 255;
        float uo[16];
        #pragma unroll
        for (int r = 0; r < 16; r++) uo[r] = __ldg(Uo + (size_t)a * 4096 + r * 256 + hh);
        float bov = __ldg(bo + a * 256 + hh);
        #pragma unroll 4
        for (int m = 0; m < 64; m++) {
            const float4* vr4 = (const float4*)(sX + (m * 4 + a) * 16);
            float4 v0 = vr4[0], v1 = vr4[1], v2 = vr4[2], v3 = vr4[3];
            float sacc = bov;
            sacc += v0.x * uo[0]  + v0.y * uo[1]  + v0.z * uo[2]  + v0.w * uo[3];
            sacc += v1.x * uo[4]  + v1.y * uo[5]  + v1.z * uo[6]  + v1.w * uo[7];
            sacc += v2.x * uo[8]  + v2.y * uo[9]  + v2.z * uo[10] + v2.w * uo[11];
            sacc += v3.x * uo[12] + v3.y * uo[13] + v3.z * uo[14] + v3.w * uo[15];
            out[(size_t)(b0 + m) * 1024 + q] = sacc;
        }
    }
}

extern "C" void kernel_launch(void* const* d_in, const int* in_sizes, int n_in,
                              void* d_out, int out_size) {
    const float* nh = (const float*)d_in[0];
    const float* te = (const float*)d_in[1];
    const float* U  = (const float*)d_in[2];
    const float* bB = (const float*)d_in[3];
    const float* Ut = (const float*)d_in[4];
    const float* bt = (const float*)d_in[5];
    const float* Uo = (const float*)d_in[6];
    const float* bo = (const float*)d_in[7];
    float* out = (float*)d_out;

    const int smem_bytes = (16384 + 8192 + 4096) * (int)sizeof(float); // 112 KB
    cudaFuncSetAttribute(tt_fused_kernel,
                         cudaFuncAttributeMaxDynamicSharedMemorySize, smem_bytes);
    tt_fused_kernel<<<256, THREADS, smem_bytes>>>(nh, te, U, bB, Ut, bt, Uo, bo, out);
}

// round 5
// speedup vs baseline: 2.7514x; 2.7514x over previous
#include <cuda_runtime.h>
#include <cuda_bf16.h>
#include <cstdint>

#define NG 32

// U in mma B-fragment layout: [g][kt(16)][nt(32)][lane(32)] -> uint2 {b0b1, b2b3}
__device__ uint2 g_Bhi[NG * 16 * 32 * 32];
__device__ uint2 g_Blo[NG * 16 * 32 * 32];

// ---- smem map (bytes) ----
#define OFF_BIAS 0          // 1024
#define OFF_SV   1024       // 128*65*4 = 33280
#define OFF_CSM  34304      // 128*132*4 = 67584
#define OFF_A    101888     // A frags: hi 16384 | lo 16384
#define OFF_B    134656     // B frags: hi 16384 | lo 16384
#define SMEM_SZ  167424
#define CSM_P    132
#define SV_P     65

__device__ __forceinline__ uint32_t pack_hi(float x, float y) {
    __nv_bfloat162 h = __halves2bfloat162(__float2bfloat16(x), __float2bfloat16(y));
    return *(uint32_t*)&h;
}
__device__ __forceinline__ uint32_t pack_lo(float x, float y, uint32_t hb) {
    __nv_bfloat162 h = *(__nv_bfloat162*)&hb;
    __nv_bfloat162 lo = __halves2bfloat162(
        __float2bfloat16(x - __bfloat162float(h.x)),
        __float2bfloat16(y - __bfloat162float(h.y)));
    return *(uint32_t*)&lo;
}

__device__ __forceinline__ void mma_bf16(float* c, const uint32_t* a, uint2 b) {
    asm volatile(
        "mma.sync.aligned.m16n8k16.row.col.f32.bf16.bf16.f32 "
        "{%0,%1,%2,%3}, {%4,%5,%6,%7}, {%8,%9}, {%0,%1,%2,%3};"
        : "+f"(c[0]), "+f"(c[1]), "+f"(c[2]), "+f"(c[3])
        : "r"(a[0]), "r"(a[1]), "r"(a[2]), "r"(a[3]), "r"(b.x), "r"(b.y));
}

// ---------------- prep: U[g][k][n] f32 -> B fragments (hi/lo bf16) ----------------
__global__ __launch_bounds__(256) void prep_B(const float* __restrict__ U) {
    const int blk = blockIdx.x;             // 512 = 32 g x 16 kt
    const int g = blk >> 4, kt = blk & 15;
    const float* Ug = U + (size_t)g * 256 * 272;
    #pragma unroll
    for (int ss = 0; ss < 4; ss++) {
        int s = threadIdx.x + ss * 256;     // 0..1023 = nt(32) x lane(32)
        int nt = s >> 5, l = s & 31;
        int k0 = kt * 16 + (l & 3) * 2, n0 = nt * 8 + (l >> 2);
        float u0 = __ldg(Ug + (size_t)k0 * 272 + n0);
        float u1 = __ldg(Ug + (size_t)(k0 + 1) * 272 + n0);
        float u8 = __ldg(Ug + (size_t)(k0 + 8) * 272 + n0);
        float u9 = __ldg(Ug + (size_t)(k0 + 9) * 272 + n0);
        uint32_t h0 = pack_hi(u0, u1), h1 = pack_hi(u8, u9);
        uint32_t l0 = pack_lo(u0, u1, h0), l1 = pack_lo(u8, u9, h1);
        size_t o = ((size_t)((g * 16 + kt) * 32 + nt)) * 32 + l;
        g_Bhi[o] = make_uint2(h0, h1);
        g_Blo[o] = make_uint2(l0, l1);
    }
}

// ---------------- main fused kernel ----------------
__global__ __launch_bounds__(512, 1)
void tt_main(const float* __restrict__ nh, const float* __restrict__ te,
             const float* __restrict__ bB, const float* __restrict__ Ut,
             const float* __restrict__ bt, const float* __restrict__ Uo,
             const float* __restrict__ bo, float* __restrict__ out)
{
    extern __shared__ __align__(16) char smem[];
    float* sBias = (float*)(smem + OFF_BIAS);
    float* sV    = (float*)(smem + OFF_SV);
    float* sC    = (float*)(smem + OFF_CSM);
    char*  sA    = smem + OFF_A;
    char*  sB    = smem + OFF_B;

    const int tid = threadIdx.x;
    const int l   = tid & 31, w = tid >> 5;
    const int mw  = w >> 2,  nwp = w & 3;     // warp grid 4M x 4N
    const int b0  = blockIdx.x * 128;
    const int em  = tid & 127, ejq = tid >> 7; // epilogue mapping

    // ================= v0 = te @ U_type + b_type =================
    {
        float* sTe = (float*)(smem + OFF_CSM);   // [128][68]
        float* sUt = (float*)(smem + OFF_A);     // [4][64][16]
        #pragma unroll
        for (int i = 0; i < 4; i++) {
            int idx = tid + i * 512;             // float4 idx 0..2047
            int m = idx >> 4, o = idx & 15;
            *(float4*)(sTe + m * 68 + o * 4) =
                __ldg((const float4*)(te + (size_t)(b0 + m) * 64) + o);
        }
        #pragma unroll
        for (int i = 0; i < 2; i++) {
            int idx = tid + i * 512;
            ((float4*)sUt)[idx] = __ldg((const float4*)Ut + idx);
        }
        __syncthreads();
        const int m = em, a = ejq;
        float4 q0 = __ldg((const float4*)(bt + a * 16) + 0);
        float4 q1 = __ldg((const float4*)(bt + a * 16) + 1);
        float4 q2 = __ldg((const float4*)(bt + a * 16) + 2);
        float4 q3 = __ldg((const float4*)(bt + a * 16) + 3);
        float vv[16] = {q0.x,q0.y,q0.z,q0.w, q1.x,q1.y,q1.z,q1.w,
                        q2.x,q2.y,q2.z,q2.w, q3.x,q3.y,q3.z,q3.w};
        const float* tr = sTe + m * 68;
        #pragma unroll 8
        for (int t = 0; t < 64; t++) {
            float x = tr[t];
            const float4* ur = (const float4*)(sUt + a * 1024 + t * 16);
            float4 u0 = ur[0], u1 = ur[1], u2 = ur[2], u3 = ur[3];
            vv[0]+=x*u0.x; vv[1]+=x*u0.y; vv[2]+=x*u0.z; vv[3]+=x*u0.w;
            vv[4]+=x*u1.x; vv[5]+=x*u1.y; vv[6]+=x*u1.z; vv[7]+=x*u1.w;
            vv[8]+=x*u2.x; vv[9]+=x*u2.y; vv[10]+=x*u2.z; vv[11]+=x*u2.w;
            vv[12]+=x*u3.x; vv[13]+=x*u3.y; vv[14]+=x*u3.z; vv[15]+=x*u3.w;
        }
        #pragma unroll
        for (int j = 0; j < 16; j++) sV[m * SV_P + a * 16 + j] = vv[j];
        __syncthreads();
    }

    // ================= main loop =================
    float2 pA[8];            // prefetched A (f32 pairs)
    uint2  pBh[4], pBl[4];   // prefetched B fragments

    // prefetch helper as a lambda-free macro-style block
    auto ldg_chunk = [&](int g, int npass, int kc) {
        const int c = g >> 2;
        #pragma unroll
        for (int ss = 0; ss < 2; ss++) {
            int s = tid + ss * 512;
            int tile = s >> 5, ll = s & 31;
            int ktL = tile >> 3, mt = tile & 7;
            int r0 = mt * 16 + (ll >> 2);
            int k  = kc * 64 + ktL * 16 + (ll & 3) * 2;
            const float* base = nh + ((size_t)(b0 + r0) * 8 + c) * 256 + k;
            pA[ss*4+0] = __ldg((const float2*)(base));
            pA[ss*4+1] = __ldg((const float2*)(base + 8 * 2048));
            pA[ss*4+2] = __ldg((const float2*)(base + 8));
            pA[ss*4+3] = __ldg((const float2*)(base + 8 * 2048 + 8));
        }
        #pragma unroll
        for (int ss = 0; ss < 4; ss++) {
            int s = tid + ss * 512;
            int tileL = s >> 5, ll = s & 31;
            int ktL = tileL >> 4, ntL = tileL & 15;
            size_t o = ((size_t)((g * 16 + kc * 4 + ktL) * 32 + npass * 16 + ntL)) * 32 + ll;
            pBh[ss] = __ldg(&g_Bhi[o]);
            pBl[ss] = __ldg(&g_Blo[o]);
        }
    };

    ldg_chunk(0, 0, 0);

    for (int g = 0; g < NG; g++) {
        const int a = g & 3;
        float nvp[4] = {0.f, 0.f, 0.f, 0.f};

        for (int npass = 0; npass < 2; npass++) {
            float acc[2][4][4];
            #pragma unroll
            for (int mt = 0; mt < 2; mt++)
                #pragma unroll
                for (int nt = 0; nt < 4; nt++)
                    #pragma unroll
                    for (int q = 0; q < 4; q++) acc[mt][nt][q] = 0.f;

            #pragma unroll 1
            for (int kc = 0; kc < 4; kc++) {
                __syncthreads();
                // ---- store stage from prefetch regs ----
                #pragma unroll
                for (int ss = 0; ss < 2; ss++) {
                    int s = tid + ss * 512;
                    int tile = s >> 5, ll = s & 31;
                    uint32_t h[4], lo[4];
                    #pragma unroll
                    for (int j = 0; j < 4; j++) {
                        h[j]  = pack_hi(pA[ss*4+j].x, pA[ss*4+j].y);
                        lo[j] = pack_lo(pA[ss*4+j].x, pA[ss*4+j].y, h[j]);
                    }
                    *(uint4*)(sA + tile * 512 + ll * 16) = make_uint4(h[0], h[1], h[2], h[3]);
                    *(uint4*)(sA + 16384 + tile * 512 + ll * 16) = make_uint4(lo[0], lo[1], lo[2], lo[3]);
                }
                #pragma unroll
                for (int ss = 0; ss < 4; ss++) {
                    int s = tid + ss * 512;
                    int tileL = s >> 5, ll = s & 31;
                    *(uint2*)(sB + tileL * 256 + ll * 8) = pBh[ss];
                    *(uint2*)(sB + 16384 + tileL * 256 + ll * 8) = pBl[ss];
                }
                if (npass == 0 && kc == 0 && tid < 64)
                    ((float4*)sBias)[tid] = __ldg((const float4*)(bB + (size_t)g * 272) + tid);
                // ---- prefetch next chunk ----
                {
                    int q = ((g * 2 + npass) * 4 + kc) + 1;
                    if (q < 256) ldg_chunk(q >> 3, (q >> 2) & 1, q & 3);
                }
                __syncthreads();
                // ---- compute: 4 k-tiles x 3 products ----
                #pragma unroll
                for (int ktL = 0; ktL < 4; ktL++) {
                    uint32_t Ah[2][4], Al[2][4];
                    *(uint4*)Ah[0] = *(uint4*)(sA + (ktL*8 + mw*2    ) * 512 + l * 16);
                    *(uint4*)Ah[1] = *(uint4*)(sA + (ktL*8 + mw*2 + 1) * 512 + l * 16);
                    *(uint4*)Al[0] = *(uint4*)(sA + 16384 + (ktL*8 + mw*2    ) * 512 + l * 16);
                    *(uint4*)Al[1] = *(uint4*)(sA + 16384 + (ktL*8 + mw*2 + 1) * 512 + l * 16);
                    uint2 Bh[4], Bl[4];
                    #pragma unroll
                    for (int nt = 0; nt < 4; nt++) {
                        Bh[nt] = *(uint2*)(sB + (ktL*16 + nwp*4 + nt) * 256 + l * 8);
                        Bl[nt] = *(uint2*)(sB + 16384 + (ktL*16 + nwp*4 + nt) * 256 + l * 8);
                    }
                    #pragma unroll
                    for (int nt = 0; nt < 4; nt++) {
                        mma_bf16(acc[0][nt], Ah[0], Bh[nt]);
                        mma_bf16(acc[1][nt], Ah[1], Bh[nt]);
                        mma_bf16(acc[0][nt], Ah[0], Bl[nt]);
                        mma_bf16(acc[1][nt], Ah[1], Bl[nt]);
                        mma_bf16(acc[0][nt], Al[0], Bh[nt]);
                        mma_bf16(acc[1][nt], Al[1], Bh[nt]);
                    }
                }
            }

            // ---- dump accums to sC [128][128(+pad)] ----
            #pragma unroll
            for (int mt = 0; mt < 2; mt++) {
                int rg = mw * 32 + mt * 16 + (l >> 2);
                #pragma unroll
                for (int nt = 0; nt < 4; nt++) {
                    int col = nwp * 32 + nt * 8 + (l & 3) * 2;
                    *(float2*)(sC + rg * CSM_P + col) =
                        make_float2(acc[mt][nt][0], acc[mt][nt][1]);
                    *(float2*)(sC + (rg + 8) * CSM_P + col) =
                        make_float2(acc[mt][nt][2], acc[mt][nt][3]);
                }
            }
            __syncthreads();
            // ---- partial scan: i-range npass*8..+8 ----
            #pragma unroll
            for (int i = 0; i < 8; i++) {
                int ig = npass * 8 + i;
                float coef = sV[em * SV_P + a * 16 + ig] + ((ig == 15) ? 1.f : 0.f);
                float4 cc = *(float4*)(sC + em * CSM_P + i * 16 + ejq * 4);
                nvp[0] += coef * (cc.x + sBias[ig * 16 + ejq * 4 + 0]);
                nvp[1] += coef * (cc.y + sBias[ig * 16 + ejq * 4 + 1]);
                nvp[2] += coef * (cc.z + sBias[ig * 16 + ejq * 4 + 2]);
                nvp[3] += coef * (cc.w + sBias[ig * 16 + ejq * 4 + 3]);
            }
        }
        __syncthreads();   // all coef reads of sV[a] done
        sV[em * SV_P + a * 16 + ejq * 4 + 0] = nvp[0];
        sV[em * SV_P + a * 16 + ejq * 4 + 1] = nvp[1];
        sV[em * SV_P + a * 16 + ejq * 4 + 2] = nvp[2];
        sV[em * SV_P + a * 16 + ejq * 4 + 3] = nvp[3];
    }
    __syncthreads();

    // ================= output projection =================
    {
        const int a = tid >> 7, h2 = (tid & 127) * 2;
        float2 uo[16];
        #pragma unroll
        for (int r = 0; r < 16; r++)
            uo[r] = __ldg((const float2*)(Uo + ((size_t)a * 16 + r) * 256 + h2));
        float2 b2 = __ldg((const float2*)(bo + a * 256 + h2));
        #pragma unroll 2
        for (int m = 0; m < 128; m++) {
            float sx = b2.x, sy = b2.y;
            const float* vr = sV + m * SV_P + a * 16;
            #pragma unroll
            for (int r = 0; r < 16; r++) {
                float vv = vr[r];
                sx += vv * uo[r].x; sy += vv * uo[r].y;
            }
            *(float2*)(out + (size_t)(b0 + m) * 1024 + a * 256 + h2) = make_float2(sx, sy);
        }
    }
}

extern "C" void kernel_launch(void* const* d_in, const int* in_sizes, int n_in,
                              void* d_out, int out_size) {
    const float* nh = (const float*)d_in[0];
    const float* te = (const float*)d_in[1];
    const float* U  = (const float*)d_in[2];
    const float* bB = (const float*)d_in[3];
    const float* Ut = (const float*)d_in[4];
    const float* bt = (const float*)d_in[5];
    const float* Uo = (const float*)d_in[6];
    const float* bo = (const float*)d_in[7];
    float* out = (float*)d_out;

    prep_B<<<512, 256>>>(U);
    cudaFuncSetAttribute(tt_main, cudaFuncAttributeMaxDynamicSharedMemorySize, SMEM_SZ);
    tt_main<<<128, 512, SMEM_SZ>>>(nh, te, bB, Ut, bt, Uo, bo, out);
}

// round 6
// speedup vs baseline: 3.6068x; 1.3109x over previous
#include <cuda_runtime.h>
#include <cuda_bf16.h>
#include <cstdint>

#define NG 32
#define SV_P 65

// A in mma A-fragment layout, hi/lo bf16: [c(8)][mt(1024)][kt(16)][lane(32)] uint4
__device__ uint4 g_Ahi[8 * 1024 * 16 * 32];
__device__ uint4 g_Alo[8 * 1024 * 16 * 32];
// B fragments hi/lo interleaved: [g(32)][kt(16)][nt(32)][lane(32)] uint4 {h0,h1,l0,l1}
__device__ uint4 g_Bf[NG * 16 * 32 * 32];

// ---- smem map (bytes) ----
#define OFF_BIAS 0          // 1024
#define OFF_SV   1024       // 128*65*4 = 33280
#define OFF_RED  34304      // 32768 (also v0's sTe scratch)
#define OFF_SA   67072      // 2 x 32768 (hi 16K | lo 16K per buf)
#define OFF_SB   132608     // 2 x 32768
#define SMEM_SZ  198144

__device__ __forceinline__ uint32_t s2u(const void* p) {
    uint32_t a;
    asm("{ .reg .u64 t; cvta.to.shared.u64 t, %1; cvt.u32.u64 %0, t; }" : "=r"(a) : "l"(p));
    return a;
}
__device__ __forceinline__ uint32_t pack_hi(float x, float y) {
    __nv_bfloat162 h = __halves2bfloat162(__float2bfloat16(x), __float2bfloat16(y));
    return *(uint32_t*)&h;
}
__device__ __forceinline__ uint32_t pack_lo(float x, float y, uint32_t hb) {
    __nv_bfloat162 h = *(__nv_bfloat162*)&hb;
    __nv_bfloat162 lo = __halves2bfloat162(
        __float2bfloat16(x - __bfloat162float(h.x)),
        __float2bfloat16(y - __bfloat162float(h.y)));
    return *(uint32_t*)&lo;
}
__device__ __forceinline__ void mma_bf16(float* c, const uint32_t* a, uint32_t b0, uint32_t b1) {
    asm volatile(
        "mma.sync.aligned.m16n8k16.row.col.f32.bf16.bf16.f32 "
        "{%0,%1,%2,%3}, {%4,%5,%6,%7}, {%8,%9}, {%0,%1,%2,%3};"
        : "+f"(c[0]), "+f"(c[1]), "+f"(c[2]), "+f"(c[3])
        : "r"(a[0]), "r"(a[1]), "r"(a[2]), "r"(a[3]), "r"(b0), "r"(b1));
}
__device__ __forceinline__ void cpa16(uint32_t dst, const void* src) {
    asm volatile("cp.async.cg.shared.global [%0], [%1], 16;" :: "r"(dst), "l"(src) : "memory");
}
#define CP_COMMIT() asm volatile("cp.async.commit_group;" ::: "memory")
#define CP_WAIT0()  asm volatile("cp.async.wait_group 0;" ::: "memory")

// ---------------- prep_A: nh f32 -> A fragments hi/lo ----------------
__global__ __launch_bounds__(256) void prep_A(const float* __restrict__ nh) {
    const int blk = blockIdx.x;              // 8192 = c(8) x mt(1024)
    const int c = blk >> 10, mt = blk & 1023;
    #pragma unroll
    for (int s = 0; s < 2; s++) {
        int u = threadIdx.x + s * 256;       // kt(16) x lane(32)
        int kt = u >> 5, l = u & 31;
        int row = mt * 16 + (l >> 2);
        int k = kt * 16 + (l & 3) * 2;
        const float* p = nh + ((size_t)row * 8 + c) * 256 + k;
        float2 x0 = __ldg((const float2*)p);                   // (r,   k)
        float2 x1 = __ldg((const float2*)(p + 8 * 2048));      // (r+8, k)
        float2 x2 = __ldg((const float2*)(p + 8));             // (r,   k+8)
        float2 x3 = __ldg((const float2*)(p + 8 * 2048 + 8));  // (r+8, k+8)
        uint32_t h0 = pack_hi(x0.x, x0.y), h1 = pack_hi(x1.x, x1.y);
        uint32_t h2 = pack_hi(x2.x, x2.y), h3 = pack_hi(x3.x, x3.y);
        size_t o = ((size_t)(c * 1024 + mt) * 16 + kt) * 32 + l;
        g_Ahi[o] = make_uint4(h0, h1, h2, h3);
        g_Alo[o] = make_uint4(pack_lo(x0.x, x0.y, h0), pack_lo(x1.x, x1.y, h1),
                              pack_lo(x2.x, x2.y, h2), pack_lo(x3.x, x3.y, h3));
    }
}

// ---------------- prep_B: U f32 -> B fragments hi/lo interleaved ----------------
__global__ __launch_bounds__(256) void prep_B(const float* __restrict__ U) {
    const int blk = blockIdx.x;              // 512 = g(32) x kt(16)
    const int g = blk >> 4, kt = blk & 15;
    const float* Ug = U + (size_t)g * 256 * 272;
    #pragma unroll
    for (int s = 0; s < 4; s++) {
        int u = threadIdx.x + s * 256;       // nt(32) x lane(32)
        int nt = u >> 5, l = u & 31;
        int k0 = kt * 16 + (l & 3) * 2, n0 = nt * 8 + (l >> 2);
        float u0 = __ldg(Ug + (size_t)k0 * 272 + n0);
        float u1 = __ldg(Ug + (size_t)(k0 + 1) * 272 + n0);
        float u8 = __ldg(Ug + (size_t)(k0 + 8) * 272 + n0);
        float u9 = __ldg(Ug + (size_t)(k0 + 9) * 272 + n0);
        uint32_t h0 = pack_hi(u0, u1), h1 = pack_hi(u8, u9);
        uint32_t l0 = pack_lo(u0, u1, h0), l1 = pack_lo(u8, u9, h1);
        g_Bf[((size_t)(g * 16 + kt) * 32 + nt) * 32 + l] = make_uint4(h0, h1, l0, l1);
    }
}

// ---------------- main fused kernel ----------------
__global__ __launch_bounds__(512, 1)
void tt_main(const float* __restrict__ te, const float* __restrict__ bB,
             const float* __restrict__ Ut, const float* __restrict__ bt,
             const float* __restrict__ Uo, const float* __restrict__ bo,
             float* __restrict__ out)
{
    extern __shared__ __align__(16) char smem[];
    const uint32_t sbase = s2u(smem);
    float* sBias = (float*)(smem + OFF_BIAS);
    float* sV    = (float*)(smem + OFF_SV);
    float* red   = (float*)(smem + OFF_RED);

    const int tid = threadIdx.x;
    const int l   = tid & 31, w = tid >> 5;
    const int mw  = w >> 2,  nwp = w & 3;       // warp grid 4M x 4N
    const int b0  = blockIdx.x * 128;
    const int mt0 = blockIdx.x * 8;

    // ================= v0 = te @ U_type + b_type =================
    {
        float* sUt = (float*)(smem + OFF_SA);   // 4096 floats
        float* sTe = red;                       // 128x64, float4-rotated
        #pragma unroll
        for (int i = 0; i < 2; i++) {
            int idx = tid + i * 512;
            ((float4*)sUt)[idx] = __ldg((const float4*)Ut + idx);
        }
        #pragma unroll
        for (int i = 0; i < 4; i++) {
            int u = tid + i * 512;              // 2048 float4 units
            int m = u >> 4, t4 = u & 15;
            *(float4*)(sTe + m * 64 + ((t4 + m) & 15) * 4) =
                __ldg((const float4*)(te + (size_t)(b0 + m) * 64) + t4);
        }
        __syncthreads();
        const int m = tid & 127, aa = tid >> 7;
        float4 q0 = __ldg((const float4*)(bt + aa * 16) + 0);
        float4 q1 = __ldg((const float4*)(bt + aa * 16) + 1);
        float4 q2 = __ldg((const float4*)(bt + aa * 16) + 2);
        float4 q3 = __ldg((const float4*)(bt + aa * 16) + 3);
        float vv[16] = {q0.x,q0.y,q0.z,q0.w, q1.x,q1.y,q1.z,q1.w,
                        q2.x,q2.y,q2.z,q2.w, q3.x,q3.y,q3.z,q3.w};
        #pragma unroll 4
        for (int t4 = 0; t4 < 16; t4++) {
            float4 xv = *(float4*)(sTe + m * 64 + ((t4 + m) & 15) * 4);
            float xs[4] = {xv.x, xv.y, xv.z, xv.w};
            #pragma unroll
            for (int e = 0; e < 4; e++) {
                float x = xs[e];
                const float4* ur = (const float4*)(sUt + aa * 1024 + (t4 * 4 + e) * 16);
                float4 u0 = ur[0], u1 = ur[1], u2 = ur[2], u3 = ur[3];
                vv[0]+=x*u0.x; vv[1]+=x*u0.y; vv[2]+=x*u0.z; vv[3]+=x*u0.w;
                vv[4]+=x*u1.x; vv[5]+=x*u1.y; vv[6]+=x*u1.z; vv[7]+=x*u1.w;
                vv[8]+=x*u2.x; vv[9]+=x*u2.y; vv[10]+=x*u2.z; vv[11]+=x*u2.w;
                vv[12]+=x*u3.x; vv[13]+=x*u3.y; vv[14]+=x*u3.z; vv[15]+=x*u3.w;
            }
        }
        #pragma unroll
        for (int j = 0; j < 16; j++) sV[m * SV_P + aa * 16 + j] = vv[j];
        __syncthreads();
    }

    // ================= pipeline =================
    auto issue = [&](int q) {
        const int g = q >> 3, npass = (q >> 2) & 1, kc = q & 3, buf = q & 1;
        const int c = g >> 2;
        const uint32_t aDst = sbase + OFF_SA + buf * 32768;
        #pragma unroll
        for (int s = 0; s < 2; s++) {
            int u = tid + s * 512;              // mtL(8) x ktL(4) x l(32)
            int mtL = u >> 7, ktL = (u >> 5) & 3, ll = u & 31;
            size_t o = ((size_t)(c * 1024 + mt0 + mtL) * 16 + kc * 4 + ktL) * 32 + ll;
            cpa16(aDst + u * 16,         g_Ahi + o);
            cpa16(aDst + 16384 + u * 16, g_Alo + o);
        }
        const uint32_t bDst = sbase + OFF_SB + buf * 32768;
        #pragma unroll
        for (int s = 0; s < 4; s++) {
            int u = tid + s * 512;              // ktL(4) x ntL(16) x l(32)
            int ktL = u >> 9, ntL = (u >> 5) & 15, ll = u & 31;
            size_t o = ((size_t)(g * 16 + kc * 4 + ktL) * 32 + npass * 16 + ntL) * 32 + ll;
            cpa16(bDst + u * 16, g_Bf + o);
        }
        CP_COMMIT();
    };

    issue(0);

    float acc[2][4][4];
    float nvp[4] = {0.f, 0.f, 0.f, 0.f};

    #pragma unroll 1
    for (int q = 0; q < 256; q++) {
        const int g = q >> 3, npass = (q >> 2) & 1, kc = q & 3, buf = q & 1;
        const int a = g & 3;

        CP_WAIT0();
        __syncthreads();
        if (q + 1 < 256) issue(q + 1);

        if (kc == 0 && npass == 0) {
            if (tid < 64)
                ((float4*)sBias)[tid] = __ldg((const float4*)(bB + (size_t)g * 272) + tid);
            nvp[0] = nvp[1] = nvp[2] = nvp[3] = 0.f;
        }
        if (kc == 0) {
            #pragma unroll
            for (int mt = 0; mt < 2; mt++)
                #pragma unroll
                for (int nt = 0; nt < 4; nt++)
                    #pragma unroll
                    for (int e = 0; e < 4; e++) acc[mt][nt][e] = 0.f;
        }

        // ---- compute 4 k-tiles ----
        const char* sAb = smem + OFF_SA + buf * 32768;
        const char* sBb = smem + OFF_SB + buf * 32768;
        #pragma unroll
        for (int ktL = 0; ktL < 4; ktL++) {
            uint32_t Ah[2][4], Al[2][4];
            *(uint4*)Ah[0] = *(const uint4*)(sAb + (((mw*2 + 0)*4 + ktL)*32 + l)*16);
            *(uint4*)Ah[1] = *(const uint4*)(sAb + (((mw*2 + 1)*4 + ktL)*32 + l)*16);
            *(uint4*)Al[0] = *(const uint4*)(sAb + 16384 + (((mw*2 + 0)*4 + ktL)*32 + l)*16);
            *(uint4*)Al[1] = *(const uint4*)(sAb + 16384 + (((mw*2 + 1)*4 + ktL)*32 + l)*16);
            #pragma unroll
            for (int nt = 0; nt < 4; nt++) {
                uint4 Bq = *(const uint4*)(sBb + (((ktL*16 + nwp*4 + nt)*32) + l)*16);
                mma_bf16(acc[0][nt], Ah[0], Bq.x, Bq.y);
                mma_bf16(acc[1][nt], Ah[1], Bq.x, Bq.y);
                mma_bf16(acc[0][nt], Ah[0], Bq.z, Bq.w);
                mma_bf16(acc[1][nt], Ah[1], Bq.z, Bq.w);
                mma_bf16(acc[0][nt], Al[0], Bq.x, Bq.y);
                mma_bf16(acc[1][nt], Al[1], Bq.x, Bq.y);
            }
        }

        // ---- epilogue at end of each npass ----
        if (kc == 3) {
            const int i0 = npass * 8 + nwp * 2, i1 = i0 + 1;
            const int j0 = (l & 3) * 2;
            float2 b00 = *(float2*)(sBias + i0 * 16 + j0);
            float2 b01 = *(float2*)(sBias + i1 * 16 + j0);
            float2 b10 = *(float2*)(sBias + i0 * 16 + j0 + 8);
            float2 b11 = *(float2*)(sBias + i1 * 16 + j0 + 8);
            const float add1 = (i1 == 15) ? 1.f : 0.f;
            const int rbase = mw * 32 + (l >> 2);
            #pragma unroll
            for (int p = 0; p < 4; p++) {
                int row = rbase + p * 8;
                float c0 = sV[row * SV_P + a * 16 + i0];
                float c1 = sV[row * SV_P + a * 16 + i1] + add1;
                int mt = p >> 1, h = (p & 1) * 2;
                float2 pj, pk;
                pj.x = c0 * (acc[mt][0][h+0] + b00.x) + c1 * (acc[mt][2][h+0] + b01.x);
                pj.y = c0 * (acc[mt][0][h+1] + b00.y) + c1 * (acc[mt][2][h+1] + b01.y);
                pk.x = c0 * (acc[mt][1][h+0] + b10.x) + c1 * (acc[mt][3][h+0] + b11.x);
                pk.y = c0 * (acc[mt][1][h+1] + b10.y) + c1 * (acc[mt][3][h+1] + b11.y);
                *(float2*)(red + (nwp * 128 + row) * 16 + j0)     = pj;
                *(float2*)(red + (nwp * 128 + row) * 16 + j0 + 8) = pk;
            }
            __syncthreads();
            {
                int row = tid & 127, jq = tid >> 7;
                float4 r0 = *(float4*)(red + (0 * 128 + row) * 16 + jq * 4);
                float4 r1 = *(float4*)(red + (1 * 128 + row) * 16 + jq * 4);
                float4 r2 = *(float4*)(red + (2 * 128 + row) * 16 + jq * 4);
                float4 r3 = *(float4*)(red + (3 * 128 + row) * 16 + jq * 4);
                nvp[0] += r0.x + r1.x + r2.x + r3.x;
                nvp[1] += r0.y + r1.y + r2.y + r3.y;
                nvp[2] += r0.z + r1.z + r2.z + r3.z;
                nvp[3] += r0.w + r1.w + r2.w + r3.w;
                if (npass == 1) {
                    sV[row * SV_P + a * 16 + jq * 4 + 0] = nvp[0];
                    sV[row * SV_P + a * 16 + jq * 4 + 1] = nvp[1];
                    sV[row * SV_P + a * 16 + jq * 4 + 2] = nvp[2];
                    sV[row * SV_P + a * 16 + jq * 4 + 3] = nvp[3];
                }
            }
        }
    }
    __syncthreads();

    // ================= output projection =================
    {
        float* sUo = (float*)(smem + OFF_SA);           // 16384 floats
        float* sBo = (float*)(smem + OFF_SA + 65536);   // 1024 floats (buf1 area)
        #pragma unroll
        for (int i = 0; i < 8; i++) {
            int idx = tid + i * 512;
            ((float4*)sUo)[idx] = __ldg((const float4*)Uo + idx);
        }
        if (tid < 256) ((float4*)sBo)[tid] = __ldg((const float4*)bo + tid);
        __syncthreads();
        const int a = tid >> 7, h2 = (tid & 127) * 2;
        float2 uo[16];
        #pragma unroll
        for (int r = 0; r < 16; r++)
            uo[r] = *(float2*)(sUo + (a * 16 + r) * 256 + h2);
        float2 b2 = *(float2*)(sBo + a * 256 + h2);
        #pragma unroll 2
        for (int m = 0; m < 128; m++) {
            float sx = b2.x, sy = b2.y;
            const float* vr = sV + m * SV_P + a * 16;
            #pragma unroll
            for (int r = 0; r < 16; r++) {
                float vvv = vr[r];
                sx += vvv * uo[r].x; sy += vvv * uo[r].y;
            }
            *(float2*)(out + (size_t)(b0 + m) * 1024 + a * 256 + h2) = make_float2(sx, sy);
        }
    }
}

extern "C" void kernel_launch(void* const* d_in, const int* in_sizes, int n_in,
                              void* d_out, int out_size) {
    const float* nh = (const float*)d_in[0];
    const float* te = (const float*)d_in[1];
    const float* U  = (const float*)d_in[2];
    const float* bB = (const float*)d_in[3];
    const float* Ut = (const float*)d_in[4];
    const float* bt = (const float*)d_in[5];
    const float* Uo = (const float*)d_in[6];
    const float* bo = (const float*)d_in[7];
    float* out = (float*)d_out;

    prep_A<<<8192, 256>>>(nh);
    prep_B<<<512, 256>>>(U);
    cudaFuncSetAttribute(tt_main, cudaFuncAttributeMaxDynamicSharedMemorySize, SMEM_SZ);
    tt_main<<<128, 512, SMEM_SZ>>>(te, bB, Ut, bt, Uo, bo, out);
}